// round 12
// baseline (speedup 1.0000x reference)
#include <cuda_runtime.h>
#include <math.h>

#define BATCH 8
#define T 2048
#define C 1024
#define H 64

// Scratch: projected k,v (tf32 bit patterns) and split-KV partials.
__device__ float g_k[BATCH * T * H];
__device__ float g_v[BATCH * T * H];
#define NCHUNK 4
#define CHUNK_TILES 8
__device__ float g_po[BATCH * NCHUNK * T * H];   // [b][c][row][h], unnormalized
__device__ float g_pm[BATCH * T * NCHUNK];       // base-2 running max
__device__ float g_pl[BATCH * T * NCHUNK];       // running denom

__device__ __forceinline__ unsigned f2tf32(float x) {
    unsigned r;
    asm("cvt.rna.tf32.f32 %0, %1;" : "=r"(r) : "f"(x));
    return r;
}

__device__ __forceinline__ void mma_tf32(float* d,
                                         const unsigned* a,
                                         unsigned b0, unsigned b1) {
    asm volatile(
        "mma.sync.aligned.m16n8k8.row.col.f32.tf32.tf32.f32 "
        "{%0,%1,%2,%3}, {%4,%5,%6,%7}, {%8,%9}, {%0,%1,%2,%3};"
        : "+f"(d[0]), "+f"(d[1]), "+f"(d[2]), "+f"(d[3])
        : "r"(a[0]), "r"(a[1]), "r"(a[2]), "r"(a[3]), "r"(b0), "r"(b1));
}

// ---------------------------------------------------------------------------
// Projection: BM=64, BN=128, BK=32, 256 threads (8 warps: 4 row-strips x 2
// col-halves), warp tile 16x64 (mf=1, nf=8). Swizzled MMA-native smem layouts:
//   Aperm[strip(4)][ks(4)][lane(32)] : float4
//   Bperm[nh(2)][nf(8)][ks(4)][lane(32)] : uint2
// Grid 256 (>148 SMs), 2 CTAs/SM via launch_bounds reg cap.
// ---------------------------------------------------------------------------
#define PBM 64
#define PBK 32
#define A_WORDS (4 * 4 * 32 * 4)           // 2048 words = 8 KB
#define B_WORDS (2 * 8 * 4 * 32 * 2)       // 4096 words = 16 KB
#define PROJ_SMEM (2 * (A_WORDS + B_WORDS) * 4)   // 48 KB

__global__ void __launch_bounds__(256, 2) proj_kernel(const float* __restrict__ x,
                                                      const float* __restrict__ Wk,
                                                      const float* __restrict__ Wv) {
    extern __shared__ unsigned psm[];
    unsigned* Ab = psm;                 // 2 x A_WORDS
    unsigned* Bb = psm + 2 * A_WORDS;   // 2 x B_WORDS

    const int tid = threadIdx.x;
    const int wid = tid >> 5;
    const int lane = tid & 31;
    const int g = lane >> 2;
    const int t = lane & 3;
    const int wr = wid >> 1;        // 0..3 : 16-row strip
    const int wc = wid & 1;         // 0..1 : 64-col half
    const int m0 = blockIdx.x * PBM;

    // Staging geometry (rows ar + 32*l; cols ac..ac+3)
    const int ar = tid >> 3;              // 0..31
    const int ac = (tid & 7) * 4;         // 0..28
    const int aks = ac >> 3;              // 0..3
    const int aehi = (ac >> 2) & 1;
    const int ag = ar & 7;
    const int aelo = (ar >> 3) & 1;
    const int asm0 = ar >> 4;             // 0..1  (A strip = asm0 + 2*l, l<2)
    const int bnf0 = (ar >> 3) & 7;       // B: nf = (bnf0 + 4*l) & 7 ; nh = l>>1

    const float* bsrc[4];
#pragma unroll
    for (int l = 0; l < 4; l++) {
        int n = ar + 32 * l;
        bsrc[l] = (n < 64) ? (Wk + (size_t)n * C) : (Wv + (size_t)(n - 64) * C);
    }

    float4 pa[2], pb[4];
#pragma unroll
    for (int l = 0; l < 2; l++)
        pa[l] = *reinterpret_cast<const float4*>(x + (size_t)(m0 + ar + 32 * l) * C + ac);
#pragma unroll
    for (int l = 0; l < 4; l++)
        pb[l] = *reinterpret_cast<const float4*>(bsrc[l] + ac);

    auto stage = [&](unsigned* As, unsigned* Bs) {
#pragma unroll
        for (int l = 0; l < 2; l++) {
            float va[4] = {pa[l].x, pa[l].y, pa[l].z, pa[l].w};
            const int sm = asm0 + 2 * l;
            unsigned abase = ((sm * 4 + aks) * 32 + ag * 4);
#pragma unroll
            for (int i = 0; i < 4; i++)
                As[(abase + (i ^ aks)) * 4 + aelo + 2 * aehi] = f2tf32(va[i]);
        }
#pragma unroll
        for (int l = 0; l < 4; l++) {
            float vb[4] = {pb[l].x, pb[l].y, pb[l].z, pb[l].w};
            const int nf = (bnf0 + 4 * l) & 7;
            const int nh = l >> 1;
            unsigned bbase = (((nh * 8 + nf) * 4 + aks) * 32 + ag * 4);
#pragma unroll
            for (int i = 0; i < 4; i++)
                Bs[(bbase + (i ^ aks)) * 2 + aehi] = f2tf32(vb[i]);
        }
    };

    stage(Ab, Bb);

    float acc[8][4];
#pragma unroll
    for (int nf = 0; nf < 8; nf++)
#pragma unroll
        for (int e = 0; e < 4; e++) acc[nf][e] = 0.f;

    const int NT = C / PBK;  // 32
    for (int i = 0; i < NT; i++) {
        __syncthreads();
        const int cur = i & 1;
        unsigned* As = Ab + cur * A_WORDS;
        unsigned* Bs = Bb + cur * B_WORDS;

        if (i + 1 < NT) {
            const int k0n = (i + 1) * PBK;
#pragma unroll
            for (int l = 0; l < 2; l++)
                pa[l] = *reinterpret_cast<const float4*>(x + (size_t)(m0 + ar + 32 * l) * C + k0n + ac);
#pragma unroll
            for (int l = 0; l < 4; l++)
                pb[l] = *reinterpret_cast<const float4*>(bsrc[l] + k0n + ac);
        }

#pragma unroll
        for (int ks = 0; ks < 4; ks++) {
            unsigned a[4];
            {
                float4 af = *reinterpret_cast<const float4*>(
                    As + ((wr * 4 + ks) * 32 + (lane ^ ks)) * 4);
                a[0] = __float_as_uint(af.x);
                a[1] = __float_as_uint(af.y);
                a[2] = __float_as_uint(af.z);
                a[3] = __float_as_uint(af.w);
            }
#pragma unroll
            for (int nf = 0; nf < 8; nf++) {
                uint2 bb = *reinterpret_cast<const uint2*>(
                    Bs + (((wc * 8 + nf) * 4 + ks) * 32 + (lane ^ ks)) * 2);
                mma_tf32(acc[nf], a, bb.x, bb.y);
            }
        }

        if (i + 1 < NT) {
            unsigned* An = Ab + ((i + 1) & 1) * A_WORDS;
            unsigned* Bn = Bb + ((i + 1) & 1) * B_WORDS;
            stage(An, Bn);
        }
    }

    // Epilogue: store tf32 bit patterns (consumers are tf32 mma only)
    float* dst = (wc == 0) ? g_k : g_v;
    const int r0 = m0 + wr * 16;
#pragma unroll
    for (int nf = 0; nf < 8; nf++) {
        int col = nf * 8 + 2 * t;
        *reinterpret_cast<float2*>(dst + (size_t)(r0 + g) * H + col) =
            make_float2(__uint_as_float(f2tf32(acc[nf][0])),
                        __uint_as_float(f2tf32(acc[nf][1])));
        *reinterpret_cast<float2*>(dst + (size_t)(r0 + g + 8) * H + col) =
            make_float2(__uint_as_float(f2tf32(acc[nf][2])),
                        __uint_as_float(f2tf32(acc[nf][3])));
    }
}

// ---------------------------------------------------------------------------
// Attention pass 1: split-KV. CTA = (qt, chunk, b); BQ=64 (4 warps x 16 rows),
// chunk = up to 8 kv-tiles of BK=64. K/V/Q already tf32 bits -> pure copies.
// ---------------------------------------------------------------------------
#define BQ 64
#define BK 64
#define KSTR 68
#define VSTR 72
#define ATTN_SMEM ((64 * KSTR + 64 * VSTR + 4 * 16 * KSTR) * 4)
#define LOG2E 1.4426950408889634f

__global__ void __launch_bounds__(128) attn_chunk_kernel() {
    const int qt = 31 - (int)blockIdx.x;   // heavy-first
    const int chunk = blockIdx.y;
    if (chunk * CHUNK_TILES > qt) return;
    const int b = blockIdx.z;

    extern __shared__ unsigned char smraw[];
    unsigned* Ks = reinterpret_cast<unsigned*>(smraw);       // [j][h] stride 68
    unsigned* Vs = Ks + 64 * KSTR;                           // [j][h] stride 72
    float* PsAll = reinterpret_cast<float*>(Vs + 64 * VSTR); // [warp][16][68]

    const int tid = threadIdx.x;
    const int wid = tid >> 5;
    const int lane = tid & 31;
    const int g = lane >> 2;
    const int t = lane & 3;
    const int q0 = qt * BQ;

    float* Ps = PsAll + wid * 16 * KSTR;
    const float* kb = g_k + (size_t)b * T * H;
    const float* vb = g_v + (size_t)b * T * H;

    const int kt0 = chunk * CHUNK_TILES;
    const int ktend = min(qt, kt0 + CHUNK_TILES - 1);
    const int niter = ktend - kt0 + 1;

    const int qra = q0 + wid * 16 + g;
    const int qrb = qra + 8;
    unsigned qa[8][4];
#pragma unroll
    for (int kf = 0; kf < 8; kf++) {
        qa[kf][0] = __float_as_uint(kb[(size_t)qra * H + kf * 8 + t]);
        qa[kf][1] = __float_as_uint(kb[(size_t)qrb * H + kf * 8 + t]);
        qa[kf][2] = __float_as_uint(kb[(size_t)qra * H + kf * 8 + t + 4]);
        qa[kf][3] = __float_as_uint(kb[(size_t)qrb * H + kf * 8 + t + 4]);
    }

    const int sj = tid >> 4;
    const int shc = (tid & 15) * 4;

    float4 pk[8], pv[8];
    {
        const int j0g = kt0 * BK;
#pragma unroll
        for (int l = 0; l < 8; l++) {
            int j = sj + l * 8;
            pk[l] = *reinterpret_cast<const float4*>(kb + (size_t)(j0g + j) * H + shc);
            pv[l] = *reinterpret_cast<const float4*>(vb + (size_t)(j0g + j) * H + shc);
        }
    }

    float o[8][4];
#pragma unroll
    for (int nf = 0; nf < 8; nf++)
#pragma unroll
        for (int e = 0; e < 4; e++) o[nf][e] = 0.f;
    float m_i[2] = {-INFINITY, -INFINITY};
    float l_i[2] = {0.f, 0.f};

    const float S2 = 0.125f * LOG2E;

    for (int it = 0; it < niter; it++) {
        const int kvt = kt0 + it;
        const int j0g = kvt * BK;

#pragma unroll
        for (int l = 0; l < 8; l++) {
            int j = sj + l * 8;
            *reinterpret_cast<float4*>(&Ks[j * KSTR + shc]) = pk[l];
            *reinterpret_cast<float4*>(&Vs[j * VSTR + shc]) = pv[l];
        }
        __syncthreads();

        if (it + 1 < niter) {
            const int jn = (kvt + 1) * BK;
#pragma unroll
            for (int l = 0; l < 8; l++) {
                int j = sj + l * 8;
                pk[l] = *reinterpret_cast<const float4*>(kb + (size_t)(jn + j) * H + shc);
                pv[l] = *reinterpret_cast<const float4*>(vb + (size_t)(jn + j) * H + shc);
            }
        }

        // S = Q @ K^T (16x64 per warp)
        float s[8][4];
#pragma unroll
        for (int nf = 0; nf < 8; nf++)
#pragma unroll
            for (int e = 0; e < 4; e++) s[nf][e] = 0.f;
#pragma unroll
        for (int kf = 0; kf < 8; kf++) {
            const int kk = kf * 8;
#pragma unroll
            for (int nf = 0; nf < 8; nf++) {
                unsigned b0 = Ks[(nf * 8 + g) * KSTR + kk + t];
                unsigned b1 = Ks[(nf * 8 + g) * KSTR + kk + t + 4];
                mma_tf32(s[nf], qa[kf], b0, b1);
            }
        }

        const bool needm = (kvt == qt);
#pragma unroll
        for (int nf = 0; nf < 8; nf++)
#pragma unroll
            for (int e = 0; e < 4; e++) {
                int col = j0g + nf * 8 + 2 * t + (e & 1);
                int row = (e & 2) ? qrb : qra;
                float v = s[nf][e] * S2;
                if (needm && col > row) v = -INFINITY;
                s[nf][e] = v;
            }

        // Online softmax (base 2); P stored pre-converted to tf32 bits
#pragma unroll
        for (int h2 = 0; h2 < 2; h2++) {
            const int e0 = h2 * 2;
            float rm = -INFINITY;
#pragma unroll
            for (int nf = 0; nf < 8; nf++)
                rm = fmaxf(rm, fmaxf(s[nf][e0], s[nf][e0 + 1]));
            rm = fmaxf(rm, __shfl_xor_sync(0xFFFFFFFFu, rm, 1));
            rm = fmaxf(rm, __shfl_xor_sync(0xFFFFFFFFu, rm, 2));
            float mn = fmaxf(m_i[h2], rm);
            float al = exp2f(m_i[h2] - mn);
            float ps = 0.f;
#pragma unroll
            for (int nf = 0; nf < 8; nf++) {
                float p0 = __uint_as_float(f2tf32(exp2f(s[nf][e0] - mn)));
                float p1 = __uint_as_float(f2tf32(exp2f(s[nf][e0 + 1] - mn)));
                ps += p0 + p1;
                o[nf][e0] *= al;
                o[nf][e0 + 1] *= al;
                *reinterpret_cast<float2*>(Ps + (g + 8 * h2) * KSTR + nf * 8 + 2 * t) =
                    make_float2(p0, p1);
            }
            ps += __shfl_xor_sync(0xFFFFFFFFu, ps, 1);
            ps += __shfl_xor_sync(0xFFFFFFFFu, ps, 2);
            l_i[h2] = l_i[h2] * al + ps;
            m_i[h2] = mn;
        }
        __syncwarp();

        // O += P @ V (A-frags raw tf32 bits; B-frags from row-major Vs)
#pragma unroll
        for (int kf = 0; kf < 8; kf++) {
            const int kk = kf * 8;
            unsigned a[4];
            a[0] = __float_as_uint(Ps[g * KSTR + kk + t]);
            a[1] = __float_as_uint(Ps[(g + 8) * KSTR + kk + t]);
            a[2] = __float_as_uint(Ps[g * KSTR + kk + t + 4]);
            a[3] = __float_as_uint(Ps[(g + 8) * KSTR + kk + t + 4]);
#pragma unroll
            for (int nf = 0; nf < 8; nf++) {
                unsigned b0 = Vs[(kk + t) * VSTR + nf * 8 + g];
                unsigned b1 = Vs[(kk + t + 4) * VSTR + nf * 8 + g];
                mma_tf32(o[nf], a, b0, b1);
            }
        }
        __syncthreads();
    }

    float* po = g_po + ((size_t)(b * NCHUNK + chunk) * T) * H;
#pragma unroll
    for (int nf = 0; nf < 8; nf++) {
        int col = nf * 8 + 2 * t;
        *reinterpret_cast<float2*>(po + (size_t)qra * H + col) = make_float2(o[nf][0], o[nf][1]);
        *reinterpret_cast<float2*>(po + (size_t)qrb * H + col) = make_float2(o[nf][2], o[nf][3]);
    }
    if (t == 0) {
        g_pm[((size_t)b * T + qra) * NCHUNK + chunk] = m_i[0];
        g_pl[((size_t)b * T + qra) * NCHUNK + chunk] = l_i[0];
        g_pm[((size_t)b * T + qrb) * NCHUNK + chunk] = m_i[1];
        g_pl[((size_t)b * T + qrb) * NCHUNK + chunk] = l_i[1];
    }
}

// ---------------------------------------------------------------------------
// Pass 2: combine partials. Warp per row, thread per 2 cols.
// ---------------------------------------------------------------------------
__global__ void __launch_bounds__(256) combine_kernel(float* __restrict__ out) {
    const int wid = threadIdx.x >> 5;
    const int lane = threadIdx.x & 31;
    const int row = blockIdx.x * 8 + wid;
    const int b = row >> 11;
    const int trow = row & 2047;
    const int qt = trow >> 6;
    const int nch = qt / CHUNK_TILES + 1;
    const int col = lane * 2;

    float m2[NCHUNK], lv[NCHUNK];
    float M2 = -INFINITY;
#pragma unroll
    for (int c = 0; c < NCHUNK; c++) {
        if (c < nch) {
            m2[c] = g_pm[((size_t)b * T + trow) * NCHUNK + c];
            lv[c] = g_pl[((size_t)b * T + trow) * NCHUNK + c];
            M2 = fmaxf(M2, m2[c]);
        }
    }
    float denom = 0.f;
    float acc0 = 0.f, acc1 = 0.f;
#pragma unroll
    for (int c = 0; c < NCHUNK; c++) {
        if (c < nch) {
            float w = exp2f(m2[c] - M2);
            denom += w * lv[c];
            float2 v = *reinterpret_cast<const float2*>(
                g_po + (((size_t)(b * NCHUNK + c) * T + trow)) * H + col);
            acc0 += w * v.x;
            acc1 += w * v.y;
        }
    }
    float inv = 1.f / denom;
    *reinterpret_cast<float2*>(out + ((size_t)b * T + trow) * H + col) =
        make_float2(acc0 * inv, acc1 * inv);
}

extern "C" void kernel_launch(void* const* d_in, const int* in_sizes, int n_in,
                              void* d_out, int out_size) {
    const float* x  = (const float*)d_in[0];
    const float* Wk = (const float*)d_in[1];
    const float* Wv = (const float*)d_in[2];
    float* out = (float*)d_out;

    cudaFuncSetAttribute(proj_kernel, cudaFuncAttributeMaxDynamicSharedMemorySize, PROJ_SMEM);
    cudaFuncSetAttribute(attn_chunk_kernel, cudaFuncAttributeMaxDynamicSharedMemorySize, ATTN_SMEM);

    proj_kernel<<<(BATCH * T) / PBM, 256, PROJ_SMEM>>>(x, Wk, Wv);
    attn_chunk_kernel<<<dim3(T / BQ, NCHUNK, BATCH), 128, ATTN_SMEM>>>();
    combine_kernel<<<(BATCH * T) / 8, 256>>>(out);
}

// round 13
// speedup vs baseline: 1.1384x; 1.1384x over previous
#include <cuda_runtime.h>
#include <math.h>

#define BATCH 8
#define T 2048
#define C 1024
#define H 64

// Scratch: projected k,v (tf32 bit patterns) and split-KV partials.
__device__ float g_k[BATCH * T * H];
__device__ float g_v[BATCH * T * H];
#define NCHUNK 4
#define CHUNK_TILES 8
__device__ float g_po[BATCH * NCHUNK * T * H];   // [b][c][row][h], unnormalized
__device__ float g_pm[BATCH * T * NCHUNK];       // base-2 running max
__device__ float g_pl[BATCH * T * NCHUNK];       // running denom

__device__ __forceinline__ unsigned f2tf32(float x) {
    unsigned r;
    asm("cvt.rna.tf32.f32 %0, %1;" : "=r"(r) : "f"(x));
    return r;
}

__device__ __forceinline__ void mma_tf32(float* d,
                                         const unsigned* a,
                                         unsigned b0, unsigned b1) {
    asm volatile(
        "mma.sync.aligned.m16n8k8.row.col.f32.tf32.tf32.f32 "
        "{%0,%1,%2,%3}, {%4,%5,%6,%7}, {%8,%9}, {%0,%1,%2,%3};"
        : "+f"(d[0]), "+f"(d[1]), "+f"(d[2]), "+f"(d[3])
        : "r"(a[0]), "r"(a[1]), "r"(a[2]), "r"(a[3]), "r"(b0), "r"(b1));
}

__device__ __forceinline__ unsigned smem_u32(const void* p) {
    return (unsigned)__cvta_generic_to_shared(p);
}
__device__ __forceinline__ void cp16(unsigned dst, const void* src) {
    asm volatile("cp.async.ca.shared.global [%0], [%1], 16;" :: "r"(dst), "l"(src));
}
__device__ __forceinline__ void cp_commit() {
    asm volatile("cp.async.commit_group;");
}
__device__ __forceinline__ void cp_wait0() {
    asm volatile("cp.async.wait_group 0;");
}

// ---------------------------------------------------------------------------
// Projection (R10-proven): BM=128, BN=128, BK=32, 256 threads, warp tile 32x64.
// Swizzled MMA-native smem layouts, double-buffered.
// ---------------------------------------------------------------------------
#define PBM 128
#define PBK 32
#define A_WORDS (8 * 4 * 32 * 4)
#define B_WORDS (2 * 8 * 4 * 32 * 2)
#define PROJ_SMEM (2 * (A_WORDS + B_WORDS) * 4)   // 64 KB

__global__ void __launch_bounds__(256) proj_kernel(const float* __restrict__ x,
                                                   const float* __restrict__ Wk,
                                                   const float* __restrict__ Wv) {
    extern __shared__ unsigned psm[];
    unsigned* Ab = psm;
    unsigned* Bb = psm + 2 * A_WORDS;

    const int tid = threadIdx.x;
    const int wid = tid >> 5;
    const int lane = tid & 31;
    const int g = lane >> 2;
    const int t = lane & 3;
    const int wr = wid >> 1;
    const int wc = wid & 1;
    const int m0 = blockIdx.x * PBM;

    const int ar = tid >> 3;
    const int ac = (tid & 7) * 4;
    const int aks = ac >> 3;
    const int aehi = (ac >> 2) & 1;
    const int ag = ar & 7;
    const int aelo = (ar >> 3) & 1;
    const int asm0 = ar >> 4;
    const int bnf0 = (ar >> 3) & 7;

    const float* bsrc[4];
#pragma unroll
    for (int l = 0; l < 4; l++) {
        int n = ar + 32 * l;
        bsrc[l] = (n < 64) ? (Wk + (size_t)n * C) : (Wv + (size_t)(n - 64) * C);
    }

    float4 pa[4], pb[4];
#pragma unroll
    for (int l = 0; l < 4; l++) {
        pa[l] = *reinterpret_cast<const float4*>(x + (size_t)(m0 + ar + 32 * l) * C + ac);
        pb[l] = *reinterpret_cast<const float4*>(bsrc[l] + ac);
    }

    auto stage = [&](unsigned* As, unsigned* Bs) {
#pragma unroll
        for (int l = 0; l < 4; l++) {
            float va[4] = {pa[l].x, pa[l].y, pa[l].z, pa[l].w};
            float vb[4] = {pb[l].x, pb[l].y, pb[l].z, pb[l].w};
            const int sm = asm0 + 2 * l;
            unsigned abase = ((sm * 4 + aks) * 32 + ag * 4);
            const int nf = (bnf0 + 4 * l) & 7;
            const int nh = l >> 1;
            unsigned bbase = (((nh * 8 + nf) * 4 + aks) * 32 + ag * 4);
#pragma unroll
            for (int i = 0; i < 4; i++) {
                As[(abase + (i ^ aks)) * 4 + aelo + 2 * aehi] = f2tf32(va[i]);
                Bs[(bbase + (i ^ aks)) * 2 + aehi] = f2tf32(vb[i]);
            }
        }
    };

    stage(Ab, Bb);

    float acc[2][8][4];
#pragma unroll
    for (int mf = 0; mf < 2; mf++)
#pragma unroll
        for (int nf = 0; nf < 8; nf++)
#pragma unroll
            for (int e = 0; e < 4; e++) acc[mf][nf][e] = 0.f;

    const int NT = C / PBK;
    for (int i = 0; i < NT; i++) {
        __syncthreads();
        const int cur = i & 1;
        unsigned* As = Ab + cur * A_WORDS;
        unsigned* Bs = Bb + cur * B_WORDS;

        if (i + 1 < NT) {
            const int k0n = (i + 1) * PBK;
#pragma unroll
            for (int l = 0; l < 4; l++) {
                pa[l] = *reinterpret_cast<const float4*>(x + (size_t)(m0 + ar + 32 * l) * C + k0n + ac);
                pb[l] = *reinterpret_cast<const float4*>(bsrc[l] + k0n + ac);
            }
        }

#pragma unroll
        for (int ks = 0; ks < 4; ks++) {
            unsigned a[2][4];
#pragma unroll
            for (int mf = 0; mf < 2; mf++) {
                const int sm = wr * 2 + mf;
                float4 af = *reinterpret_cast<const float4*>(
                    As + ((sm * 4 + ks) * 32 + (lane ^ ks)) * 4);
                a[mf][0] = __float_as_uint(af.x);
                a[mf][1] = __float_as_uint(af.y);
                a[mf][2] = __float_as_uint(af.z);
                a[mf][3] = __float_as_uint(af.w);
            }
#pragma unroll
            for (int nf = 0; nf < 8; nf++) {
                uint2 bb = *reinterpret_cast<const uint2*>(
                    Bs + (((wc * 8 + nf) * 4 + ks) * 32 + (lane ^ ks)) * 2);
#pragma unroll
                for (int mf = 0; mf < 2; mf++)
                    mma_tf32(acc[mf][nf], a[mf], bb.x, bb.y);
            }
        }

        if (i + 1 < NT) {
            unsigned* An = Ab + ((i + 1) & 1) * A_WORDS;
            unsigned* Bn = Bb + ((i + 1) & 1) * B_WORDS;
            stage(An, Bn);
        }
    }

    float* dst = (wc == 0) ? g_k : g_v;
#pragma unroll
    for (int mf = 0; mf < 2; mf++) {
        const int r0 = m0 + wr * 32 + mf * 16;
#pragma unroll
        for (int nf = 0; nf < 8; nf++) {
            int col = nf * 8 + 2 * t;
            *reinterpret_cast<float2*>(dst + (size_t)(r0 + g) * H + col) =
                make_float2(__uint_as_float(f2tf32(acc[mf][nf][0])),
                            __uint_as_float(f2tf32(acc[mf][nf][1])));
            *reinterpret_cast<float2*>(dst + (size_t)(r0 + g + 8) * H + col) =
                make_float2(__uint_as_float(f2tf32(acc[mf][nf][2])),
                            __uint_as_float(f2tf32(acc[mf][nf][3])));
        }
    }
}

// ---------------------------------------------------------------------------
// Attention pass 1: split-KV, cp.async double-buffered K/V staging.
// CTA = (qt, chunk, b); BQ=64 (4 warps x 16 rows), up to 8 kv-tiles of BK=64.
// ---------------------------------------------------------------------------
#define BQ 64
#define BK 64
#define KSTR 68
#define VSTR 72
#define KV_WORDS (64 * KSTR + 64 * VSTR)
// 2 K/V buffers + Ps: (2*8960 + 4352) * 4 = 89088 bytes
#define ATTN_SMEM ((2 * KV_WORDS + 4 * 16 * KSTR) * 4)
#define LOG2E 1.4426950408889634f

__global__ void __launch_bounds__(128) attn_chunk_kernel() {
    const int qt = 31 - (int)blockIdx.x;   // heavy-first
    const int chunk = blockIdx.y;
    if (chunk * CHUNK_TILES > qt) return;
    const int b = blockIdx.z;

    extern __shared__ unsigned char smraw[];
    unsigned* KVb = reinterpret_cast<unsigned*>(smraw);          // 2 x KV_WORDS
    float* PsAll = reinterpret_cast<float*>(KVb + 2 * KV_WORDS); // [warp][16][68]

    const int tid = threadIdx.x;
    const int wid = tid >> 5;
    const int lane = tid & 31;
    const int g = lane >> 2;
    const int t = lane & 3;
    const int q0 = qt * BQ;

    float* Ps = PsAll + wid * 16 * KSTR;
    const float* kb = g_k + (size_t)b * T * H;
    const float* vb = g_v + (size_t)b * T * H;

    const int kt0 = chunk * CHUNK_TILES;
    const int ktend = min(qt, kt0 + CHUNK_TILES - 1);
    const int niter = ktend - kt0 + 1;

    const int qra = q0 + wid * 16 + g;
    const int qrb = qra + 8;
    unsigned qa[8][4];
#pragma unroll
    for (int kf = 0; kf < 8; kf++) {
        qa[kf][0] = __float_as_uint(kb[(size_t)qra * H + kf * 8 + t]);
        qa[kf][1] = __float_as_uint(kb[(size_t)qrb * H + kf * 8 + t]);
        qa[kf][2] = __float_as_uint(kb[(size_t)qra * H + kf * 8 + t + 4]);
        qa[kf][3] = __float_as_uint(kb[(size_t)qrb * H + kf * 8 + t + 4]);
    }

    // Copy geometry: each thread moves 8 K-rows and 8 V-rows (16B each).
    const int sj = tid >> 4;          // 0..7, row j = sj + 8*l
    const int shc = (tid & 15) * 4;   // col quad

    auto issue_copy = [&](int kvt, int buf) {
        unsigned* Ks = KVb + buf * KV_WORDS;
        unsigned* Vs = Ks + 64 * KSTR;
        const int j0g = kvt * BK;
#pragma unroll
        for (int l = 0; l < 8; l++) {
            int j = sj + l * 8;
            cp16(smem_u32(&Ks[j * KSTR + shc]), kb + (size_t)(j0g + j) * H + shc);
            cp16(smem_u32(&Vs[j * VSTR + shc]), vb + (size_t)(j0g + j) * H + shc);
        }
        cp_commit();
    };

    issue_copy(kt0, 0);

    float o[8][4];
#pragma unroll
    for (int nf = 0; nf < 8; nf++)
#pragma unroll
        for (int e = 0; e < 4; e++) o[nf][e] = 0.f;
    float m_i[2] = {-INFINITY, -INFINITY};
    float l_i[2] = {0.f, 0.f};

    const float S2 = 0.125f * LOG2E;

    for (int it = 0; it < niter; it++) {
        const int kvt = kt0 + it;
        const int j0g = kvt * BK;
        const int cur = it & 1;
        unsigned* Ks = KVb + cur * KV_WORDS;
        unsigned* Vs = Ks + 64 * KSTR;

        cp_wait0();
        __syncthreads();

        if (it + 1 < niter) issue_copy(kvt + 1, cur ^ 1);

        // S = Q @ K^T (16x64 per warp)
        float s[8][4];
#pragma unroll
        for (int nf = 0; nf < 8; nf++)
#pragma unroll
            for (int e = 0; e < 4; e++) s[nf][e] = 0.f;
#pragma unroll
        for (int kf = 0; kf < 8; kf++) {
            const int kk = kf * 8;
#pragma unroll
            for (int nf = 0; nf < 8; nf++) {
                unsigned b0 = Ks[(nf * 8 + g) * KSTR + kk + t];
                unsigned b1 = Ks[(nf * 8 + g) * KSTR + kk + t + 4];
                mma_tf32(s[nf], qa[kf], b0, b1);
            }
        }

        const bool needm = (kvt == qt);
#pragma unroll
        for (int nf = 0; nf < 8; nf++)
#pragma unroll
            for (int e = 0; e < 4; e++) {
                int col = j0g + nf * 8 + 2 * t + (e & 1);
                int row = (e & 2) ? qrb : qra;
                float v = s[nf][e] * S2;
                if (needm && col > row) v = -INFINITY;
                s[nf][e] = v;
            }

        // Online softmax (base 2); P stored pre-converted to tf32 bits
#pragma unroll
        for (int h2 = 0; h2 < 2; h2++) {
            const int e0 = h2 * 2;
            float rm = -INFINITY;
#pragma unroll
            for (int nf = 0; nf < 8; nf++)
                rm = fmaxf(rm, fmaxf(s[nf][e0], s[nf][e0 + 1]));
            rm = fmaxf(rm, __shfl_xor_sync(0xFFFFFFFFu, rm, 1));
            rm = fmaxf(rm, __shfl_xor_sync(0xFFFFFFFFu, rm, 2));
            float mn = fmaxf(m_i[h2], rm);
            float al = exp2f(m_i[h2] - mn);
            float ps = 0.f;
#pragma unroll
            for (int nf = 0; nf < 8; nf++) {
                float p0 = __uint_as_float(f2tf32(exp2f(s[nf][e0] - mn)));
                float p1 = __uint_as_float(f2tf32(exp2f(s[nf][e0 + 1] - mn)));
                ps += p0 + p1;
                o[nf][e0] *= al;
                o[nf][e0 + 1] *= al;
                *reinterpret_cast<float2*>(Ps + (g + 8 * h2) * KSTR + nf * 8 + 2 * t) =
                    make_float2(p0, p1);
            }
            ps += __shfl_xor_sync(0xFFFFFFFFu, ps, 1);
            ps += __shfl_xor_sync(0xFFFFFFFFu, ps, 2);
            l_i[h2] = l_i[h2] * al + ps;
            m_i[h2] = mn;
        }
        __syncwarp();

        // O += P @ V
#pragma unroll
        for (int kf = 0; kf < 8; kf++) {
            const int kk = kf * 8;
            unsigned a[4];
            a[0] = __float_as_uint(Ps[g * KSTR + kk + t]);
            a[1] = __float_as_uint(Ps[(g + 8) * KSTR + kk + t]);
            a[2] = __float_as_uint(Ps[g * KSTR + kk + t + 4]);
            a[3] = __float_as_uint(Ps[(g + 8) * KSTR + kk + t + 4]);
#pragma unroll
            for (int nf = 0; nf < 8; nf++) {
                unsigned b0 = Vs[(kk + t) * VSTR + nf * 8 + g];
                unsigned b1 = Vs[(kk + t + 4) * VSTR + nf * 8 + g];
                mma_tf32(o[nf], a, b0, b1);
            }
        }
    }

    float* po = g_po + ((size_t)(b * NCHUNK + chunk) * T) * H;
#pragma unroll
    for (int nf = 0; nf < 8; nf++) {
        int col = nf * 8 + 2 * t;
        *reinterpret_cast<float2*>(po + (size_t)qra * H + col) = make_float2(o[nf][0], o[nf][1]);
        *reinterpret_cast<float2*>(po + (size_t)qrb * H + col) = make_float2(o[nf][2], o[nf][3]);
    }
    if (t == 0) {
        g_pm[((size_t)b * T + qra) * NCHUNK + chunk] = m_i[0];
        g_pl[((size_t)b * T + qra) * NCHUNK + chunk] = l_i[0];
        g_pm[((size_t)b * T + qrb) * NCHUNK + chunk] = m_i[1];
        g_pl[((size_t)b * T + qrb) * NCHUNK + chunk] = l_i[1];
    }
}

// ---------------------------------------------------------------------------
// Pass 2: combine partials. Warp per row, thread per 2 cols.
// ---------------------------------------------------------------------------
__global__ void __launch_bounds__(256) combine_kernel(float* __restrict__ out) {
    const int wid = threadIdx.x >> 5;
    const int lane = threadIdx.x & 31;
    const int row = blockIdx.x * 8 + wid;
    const int b = row >> 11;
    const int trow = row & 2047;
    const int qt = trow >> 6;
    const int nch = qt / CHUNK_TILES + 1;
    const int col = lane * 2;

    float m2[NCHUNK], lv[NCHUNK];
    float M2 = -INFINITY;
#pragma unroll
    for (int c = 0; c < NCHUNK; c++) {
        if (c < nch) {
            m2[c] = g_pm[((size_t)b * T + trow) * NCHUNK + c];
            lv[c] = g_pl[((size_t)b * T + trow) * NCHUNK + c];
            M2 = fmaxf(M2, m2[c]);
        }
    }
    float denom = 0.f;
    float acc0 = 0.f, acc1 = 0.f;
#pragma unroll
    for (int c = 0; c < NCHUNK; c++) {
        if (c < nch) {
            float w = exp2f(m2[c] - M2);
            denom += w * lv[c];
            float2 v = *reinterpret_cast<const float2*>(
                g_po + (((size_t)(b * NCHUNK + c) * T + trow)) * H + col);
            acc0 += w * v.x;
            acc1 += w * v.y;
        }
    }
    float inv = 1.f / denom;
    *reinterpret_cast<float2*>(out + ((size_t)b * T + trow) * H + col) =
        make_float2(acc0 * inv, acc1 * inv);
}

extern "C" void kernel_launch(void* const* d_in, const int* in_sizes, int n_in,
                              void* d_out, int out_size) {
    const float* x  = (const float*)d_in[0];
    const float* Wk = (const float*)d_in[1];
    const float* Wv = (const float*)d_in[2];
    float* out = (float*)d_out;

    cudaFuncSetAttribute(proj_kernel, cudaFuncAttributeMaxDynamicSharedMemorySize, PROJ_SMEM);
    cudaFuncSetAttribute(attn_chunk_kernel, cudaFuncAttributeMaxDynamicSharedMemorySize, ATTN_SMEM);

    proj_kernel<<<(BATCH * T) / PBM, 256, PROJ_SMEM>>>(x, Wk, Wv);
    attn_chunk_kernel<<<dim3(T / BQ, NCHUNK, BATCH), 128, ATTN_SMEM>>>();
    combine_kernel<<<(BATCH * T) / 8, 256>>>(out);
}

// round 14
// speedup vs baseline: 1.5620x; 1.3721x over previous
#include <cuda_runtime.h>
#include <cuda_fp16.h>
#include <math.h>

#define BATCH 8
#define T 2048
#define C 1024
#define H 64

// Scratch: projected k (row-major fp16), v (TRANSPOSED fp16 [b][h][t]), partials.
__device__ __half g_k2[BATCH * T * H];
__device__ __half g_vT[BATCH * H * T];
#define NCHUNK 4
#define CHUNK_TILES 8
__device__ float g_po[BATCH * NCHUNK * T * H];
__device__ float g_pm[BATCH * T * NCHUNK];
__device__ float g_pl[BATCH * T * NCHUNK];

__device__ __forceinline__ void mma_f16(float* d, const unsigned* a,
                                        unsigned b0, unsigned b1) {
    asm volatile(
        "mma.sync.aligned.m16n8k16.row.col.f32.f16.f16.f32 "
        "{%0,%1,%2,%3}, {%4,%5,%6,%7}, {%8,%9}, {%0,%1,%2,%3};"
        : "+f"(d[0]), "+f"(d[1]), "+f"(d[2]), "+f"(d[3])
        : "r"(a[0]), "r"(a[1]), "r"(a[2]), "r"(a[3]), "r"(b0), "r"(b1));
}

__device__ __forceinline__ unsigned h2u(float x, float y) {
    __half2 h = __floats2half2_rn(make_float2(x, y).x, make_float2(x, y).y);
    return *reinterpret_cast<unsigned*>(&h);
}

__device__ __forceinline__ unsigned smem_u32(const void* p) {
    return (unsigned)__cvta_generic_to_shared(p);
}
__device__ __forceinline__ void cp16(unsigned dst, const void* src) {
    asm volatile("cp.async.ca.shared.global [%0], [%1], 16;" :: "r"(dst), "l"(src));
}
__device__ __forceinline__ void cp_commit() { asm volatile("cp.async.commit_group;"); }
__device__ __forceinline__ void cp_wait0() { asm volatile("cp.async.wait_group 0;"); }

// ---------------------------------------------------------------------------
// Projection (fp16 mma): BM=128, BN=128, BK=32, 256 thr, warp tile 32x64.
// Smem rows padded to 40 halves (20 u32 = 20-bank stride -> conflict-free frags).
// Outputs: g_k2 row-major fp16; g_vT transposed fp16.
// ---------------------------------------------------------------------------
#define PBM 128
#define PBK 32
#define KP32 20                       // u32 per smem row (40 halves)
#define TILE_W (128 * KP32)           // u32 per A or B tile
#define PROJ_SMEM (4 * TILE_W * 4)    // 2 buffers x (A+B) = 40 KB

__global__ void __launch_bounds__(256) proj_kernel(const float* __restrict__ x,
                                                   const float* __restrict__ Wk,
                                                   const float* __restrict__ Wv) {
    extern __shared__ unsigned psm[];
    unsigned* Ab = psm;                // 2 x TILE_W
    unsigned* Bb = psm + 2 * TILE_W;   // 2 x TILE_W

    const int tid = threadIdx.x;
    const int wid = tid >> 5;
    const int lane = tid & 31;
    const int g = lane >> 2;
    const int t = lane & 3;
    const int wr = wid >> 1;           // 0..3
    const int wc = wid & 1;            // 0..1
    const int m0 = blockIdx.x * PBM;

    const int ar = tid >> 3;           // 0..31 (row base; +32*l)
    const int ac = (tid & 7) * 4;      // half col 0..28
    const int au = ac >> 1;            // u32 col (even)

    const float* bsrc[4];
#pragma unroll
    for (int l = 0; l < 4; l++) {
        int n = ar + 32 * l;
        bsrc[l] = (n < 64) ? (Wk + (size_t)n * C) : (Wv + (size_t)(n - 64) * C);
    }

    float4 pa[4], pb[4];
#pragma unroll
    for (int l = 0; l < 4; l++) {
        pa[l] = *reinterpret_cast<const float4*>(x + (size_t)(m0 + ar + 32 * l) * C + ac);
        pb[l] = *reinterpret_cast<const float4*>(bsrc[l] + ac);
    }

    auto stage = [&](unsigned* As, unsigned* Bs) {
#pragma unroll
        for (int l = 0; l < 4; l++) {
            int row = ar + 32 * l;
            uint2 av = make_uint2(h2u(pa[l].x, pa[l].y), h2u(pa[l].z, pa[l].w));
            uint2 bv = make_uint2(h2u(pb[l].x, pb[l].y), h2u(pb[l].z, pb[l].w));
            *reinterpret_cast<uint2*>(As + row * KP32 + au) = av;
            *reinterpret_cast<uint2*>(Bs + row * KP32 + au) = bv;
        }
    };

    stage(Ab, Bb);

    float acc[2][8][4];
#pragma unroll
    for (int mf = 0; mf < 2; mf++)
#pragma unroll
        for (int nf = 0; nf < 8; nf++)
#pragma unroll
            for (int e = 0; e < 4; e++) acc[mf][nf][e] = 0.f;

    const int NT = C / PBK;  // 32
    for (int i = 0; i < NT; i++) {
        __syncthreads();
        const int cur = i & 1;
        unsigned* As = Ab + cur * TILE_W;
        unsigned* Bs = Bb + cur * TILE_W;

        if (i + 1 < NT) {
            const int k0n = (i + 1) * PBK;
#pragma unroll
            for (int l = 0; l < 4; l++) {
                pa[l] = *reinterpret_cast<const float4*>(x + (size_t)(m0 + ar + 32 * l) * C + k0n + ac);
                pb[l] = *reinterpret_cast<const float4*>(bsrc[l] + k0n + ac);
            }
        }

#pragma unroll
        for (int ks = 0; ks < 2; ks++) {
            const int ku = ks * 8;    // u32 offset (16 halves)
            unsigned a[2][4];
#pragma unroll
            for (int mf = 0; mf < 2; mf++) {
                const int r = wr * 32 + mf * 16 + g;
                a[mf][0] = As[r * KP32 + ku + t];
                a[mf][1] = As[(r + 8) * KP32 + ku + t];
                a[mf][2] = As[r * KP32 + ku + t + 4];
                a[mf][3] = As[(r + 8) * KP32 + ku + t + 4];
            }
#pragma unroll
            for (int nf = 0; nf < 8; nf++) {
                const int n = wc * 64 + nf * 8 + g;
                unsigned b0 = Bs[n * KP32 + ku + t];
                unsigned b1 = Bs[n * KP32 + ku + t + 4];
#pragma unroll
                for (int mf = 0; mf < 2; mf++)
                    mma_f16(acc[mf][nf], a[mf], b0, b1);
            }
        }

        if (i + 1 < NT)
            stage(Ab + ((i + 1) & 1) * TILE_W, Bb + ((i + 1) & 1) * TILE_W);
    }

    // Epilogue
    const int bidx = m0 >> 11;             // batch of this tile
    const int tr0 = m0 & 2047;             // token base within batch
    if (wc == 0) {
        // k: row-major fp16
#pragma unroll
        for (int mf = 0; mf < 2; mf++) {
            const int r0 = m0 + wr * 32 + mf * 16;
#pragma unroll
            for (int nf = 0; nf < 8; nf++) {
                int col = nf * 8 + 2 * t;
                unsigned v0 = h2u(acc[mf][nf][0], acc[mf][nf][1]);
                unsigned v1 = h2u(acc[mf][nf][2], acc[mf][nf][3]);
                *reinterpret_cast<unsigned*>(&g_k2[(size_t)(r0 + g) * H + col]) = v0;
                *reinterpret_cast<unsigned*>(&g_k2[(size_t)(r0 + g + 8) * H + col]) = v1;
            }
        }
    } else {
        // v: transposed fp16 [b][h][t]
        __half* vb = g_vT + (size_t)bidx * H * T;
#pragma unroll
        for (int mf = 0; mf < 2; mf++) {
            const int r = tr0 + wr * 32 + mf * 16 + g;
#pragma unroll
            for (int nf = 0; nf < 8; nf++) {
                int col = nf * 8 + 2 * t;
                vb[(size_t)col * T + r]            = __float2half_rn(acc[mf][nf][0]);
                vb[(size_t)(col + 1) * T + r]      = __float2half_rn(acc[mf][nf][1]);
                vb[(size_t)col * T + r + 8]        = __float2half_rn(acc[mf][nf][2]);
                vb[(size_t)(col + 1) * T + r + 8]  = __float2half_rn(acc[mf][nf][3]);
            }
        }
    }
}

// ---------------------------------------------------------------------------
// Attention pass 1 (fp16 mma): split-KV, cp.async double-buffered K and Vt.
// BQ=64 (4 warps x 16 rows), BK=64. Smem rows = 72 halves (36 u32, conflict-free).
// ---------------------------------------------------------------------------
#define BQ 64
#define BK 64
#define KS32 36                        // u32 per smem row (72 halves)
#define KVW (64 * KS32 * 2)            // K + V tile, u32
#define PS_W (16 * KS32)               // per-warp P, u32
#define ATTN_SMEM ((2 * KVW + 4 * PS_W) * 4)   // 46080 B
#define LOG2E 1.4426950408889634f

__global__ void __launch_bounds__(128) attn_chunk_kernel() {
    const int qt = 31 - (int)blockIdx.x;   // heavy-first
    const int chunk = blockIdx.y;
    if (chunk * CHUNK_TILES > qt) return;
    const int b = blockIdx.z;

    extern __shared__ unsigned char smraw[];
    unsigned* KVb = reinterpret_cast<unsigned*>(smraw);     // 2 x KVW
    unsigned* PsAll = KVb + 2 * KVW;                        // 4 x PS_W

    const int tid = threadIdx.x;
    const int wid = tid >> 5;
    const int lane = tid & 31;
    const int g = lane >> 2;
    const int t = lane & 3;
    const int q0 = qt * BQ;

    unsigned* Psw = PsAll + wid * PS_W;
    const __half* kb = g_k2 + (size_t)b * T * H;
    const __half* vTb = g_vT + (size_t)b * H * T;

    const int kt0 = chunk * CHUNK_TILES;
    const int ktend = min(qt, kt0 + CHUNK_TILES - 1);
    const int niter = ktend - kt0 + 1;

    const int qra = q0 + wid * 16 + g;
    const int qrb = qra + 8;
    unsigned qa[4][4];
#pragma unroll
    for (int kf = 0; kf < 4; kf++) {
        qa[kf][0] = *reinterpret_cast<const unsigned*>(kb + (size_t)qra * H + kf * 16 + 2 * t);
        qa[kf][1] = *reinterpret_cast<const unsigned*>(kb + (size_t)qrb * H + kf * 16 + 2 * t);
        qa[kf][2] = *reinterpret_cast<const unsigned*>(kb + (size_t)qra * H + kf * 16 + 2 * t + 8);
        qa[kf][3] = *reinterpret_cast<const unsigned*>(kb + (size_t)qrb * H + kf * 16 + 2 * t + 8);
    }

    // Copy geometry: unit u = tid + 128*l -> row = u>>3 (0..63), seg = u&7 (16B).
    const int crow = tid >> 3;
    const int cseg = tid & 7;

    auto issue_copy = [&](int kvt, int buf) {
        unsigned* Ks = KVb + buf * KVW;
        unsigned* Vs = Ks + 64 * KS32;
        const int j0g = kvt * BK;
#pragma unroll
        for (int l = 0; l < 4; l++) {
            int row = crow + l * 16;
            // K tile: rows j (tokens), 128B each from row-major g_k2
            cp16(smem_u32(Ks + row * KS32 + cseg * 4),
                 kb + (size_t)(j0g + row) * H + cseg * 8);
            // V tile: rows h, window of 64 tokens from transposed g_vT
            cp16(smem_u32(Vs + row * KS32 + cseg * 4),
                 vTb + (size_t)row * T + j0g + cseg * 8);
        }
        cp_commit();
    };

    issue_copy(kt0, 0);

    float o[8][4];
#pragma unroll
    for (int nf = 0; nf < 8; nf++)
#pragma unroll
        for (int e = 0; e < 4; e++) o[nf][e] = 0.f;
    float m_i[2] = {-INFINITY, -INFINITY};
    float l_i[2] = {0.f, 0.f};

    const float S2 = 0.125f * LOG2E;

    for (int it = 0; it < niter; it++) {
        const int kvt = kt0 + it;
        const int j0g = kvt * BK;
        const int cur = it & 1;
        unsigned* Ks = KVb + cur * KVW;
        unsigned* Vs = Ks + 64 * KS32;

        cp_wait0();
        __syncthreads();

        if (it + 1 < niter) issue_copy(kvt + 1, cur ^ 1);

        // S = Q @ K^T (16x64 per warp), K=64 in 4 mma k-steps
        float s[8][4];
#pragma unroll
        for (int nf = 0; nf < 8; nf++)
#pragma unroll
            for (int e = 0; e < 4; e++) s[nf][e] = 0.f;
#pragma unroll
        for (int kf = 0; kf < 4; kf++) {
            const int ku = kf * 8;
#pragma unroll
            for (int nf = 0; nf < 8; nf++) {
                unsigned b0 = Ks[(nf * 8 + g) * KS32 + ku + t];
                unsigned b1 = Ks[(nf * 8 + g) * KS32 + ku + t + 4];
                mma_f16(s[nf], qa[kf], b0, b1);
            }
        }

        const bool needm = (kvt == qt);
#pragma unroll
        for (int nf = 0; nf < 8; nf++)
#pragma unroll
            for (int e = 0; e < 4; e++) {
                int col = j0g + nf * 8 + 2 * t + (e & 1);
                int row = (e & 2) ? qrb : qra;
                float v = s[nf][e] * S2;
                if (needm && col > row) v = -INFINITY;
                s[nf][e] = v;
            }

        // Online softmax (base 2); P stored as half2 pairs along j
#pragma unroll
        for (int h2 = 0; h2 < 2; h2++) {
            const int e0 = h2 * 2;
            float rm = -INFINITY;
#pragma unroll
            for (int nf = 0; nf < 8; nf++)
                rm = fmaxf(rm, fmaxf(s[nf][e0], s[nf][e0 + 1]));
            rm = fmaxf(rm, __shfl_xor_sync(0xFFFFFFFFu, rm, 1));
            rm = fmaxf(rm, __shfl_xor_sync(0xFFFFFFFFu, rm, 2));
            float mn = fmaxf(m_i[h2], rm);
            float al = exp2f(m_i[h2] - mn);
            float ps = 0.f;
#pragma unroll
            for (int nf = 0; nf < 8; nf++) {
                float p0 = exp2f(s[nf][e0] - mn);
                float p1 = exp2f(s[nf][e0 + 1] - mn);
                ps += p0 + p1;
                o[nf][e0] *= al;
                o[nf][e0 + 1] *= al;
                Psw[(g + 8 * h2) * KS32 + nf * 4 + t] = h2u(p0, p1);
            }
            ps += __shfl_xor_sync(0xFFFFFFFFu, ps, 1);
            ps += __shfl_xor_sync(0xFFFFFFFFu, ps, 2);
            l_i[h2] = l_i[h2] * al + ps;
            m_i[h2] = mn;
        }
        __syncwarp();

        // O += P @ V : A = P (pairs along j), B = Vt rows h
#pragma unroll
        for (int kf = 0; kf < 4; kf++) {
            const int ku = kf * 8;
            unsigned a[4];
            a[0] = Psw[g * KS32 + ku + t];
            a[1] = Psw[(g + 8) * KS32 + ku + t];
            a[2] = Psw[g * KS32 + ku + t + 4];
            a[3] = Psw[(g + 8) * KS32 + ku + t + 4];
#pragma unroll
            for (int nf = 0; nf < 8; nf++) {
                unsigned b0 = Vs[(nf * 8 + g) * KS32 + ku + t];
                unsigned b1 = Vs[(nf * 8 + g) * KS32 + ku + t + 4];
                mma_f16(o[nf], a, b0, b1);
            }
        }
    }

    float* po = g_po + ((size_t)(b * NCHUNK + chunk) * T) * H;
#pragma unroll
    for (int nf = 0; nf < 8; nf++) {
        int col = nf * 8 + 2 * t;
        *reinterpret_cast<float2*>(po + (size_t)qra * H + col) = make_float2(o[nf][0], o[nf][1]);
        *reinterpret_cast<float2*>(po + (size_t)qrb * H + col) = make_float2(o[nf][2], o[nf][3]);
    }
    if (t == 0) {
        g_pm[((size_t)b * T + qra) * NCHUNK + chunk] = m_i[0];
        g_pl[((size_t)b * T + qra) * NCHUNK + chunk] = l_i[0];
        g_pm[((size_t)b * T + qrb) * NCHUNK + chunk] = m_i[1];
        g_pl[((size_t)b * T + qrb) * NCHUNK + chunk] = l_i[1];
    }
}

// ---------------------------------------------------------------------------
// Pass 2: combine partials.
// ---------------------------------------------------------------------------
__global__ void __launch_bounds__(256) combine_kernel(float* __restrict__ out) {
    const int wid = threadIdx.x >> 5;
    const int lane = threadIdx.x & 31;
    const int row = blockIdx.x * 8 + wid;
    const int b = row >> 11;
    const int trow = row & 2047;
    const int qt = trow >> 6;
    const int nch = qt / CHUNK_TILES + 1;
    const int col = lane * 2;

    float m2[NCHUNK], lv[NCHUNK];
    float M2 = -INFINITY;
#pragma unroll
    for (int c = 0; c < NCHUNK; c++) {
        if (c < nch) {
            m2[c] = g_pm[((size_t)b * T + trow) * NCHUNK + c];
            lv[c] = g_pl[((size_t)b * T + trow) * NCHUNK + c];
            M2 = fmaxf(M2, m2[c]);
        }
    }
    float denom = 0.f;
    float acc0 = 0.f, acc1 = 0.f;
#pragma unroll
    for (int c = 0; c < NCHUNK; c++) {
        if (c < nch) {
            float w = exp2f(m2[c] - M2);
            denom += w * lv[c];
            float2 v = *reinterpret_cast<const float2*>(
                g_po + (((size_t)(b * NCHUNK + c) * T + trow)) * H + col);
            acc0 += w * v.x;
            acc1 += w * v.y;
        }
    }
    float inv = 1.f / denom;
    *reinterpret_cast<float2*>(out + ((size_t)b * T + trow) * H + col) =
        make_float2(acc0 * inv, acc1 * inv);
}

extern "C" void kernel_launch(void* const* d_in, const int* in_sizes, int n_in,
                              void* d_out, int out_size) {
    const float* x  = (const float*)d_in[0];
    const float* Wk = (const float*)d_in[1];
    const float* Wv = (const float*)d_in[2];
    float* out = (float*)d_out;

    cudaFuncSetAttribute(proj_kernel, cudaFuncAttributeMaxDynamicSharedMemorySize, PROJ_SMEM);
    cudaFuncSetAttribute(attn_chunk_kernel, cudaFuncAttributeMaxDynamicSharedMemorySize, ATTN_SMEM);

    proj_kernel<<<(BATCH * T) / PBM, 256, PROJ_SMEM>>>(x, Wk, Wv);
    attn_chunk_kernel<<<dim3(T / BQ, NCHUNK, BATCH), 128, ATTN_SMEM>>>();
    combine_kernel<<<(BATCH * T) / 8, 256>>>(out);
}